// round 3
// baseline (speedup 1.0000x reference)
#include <cuda_runtime.h>

#define N_NODES 100000
#define N_EDGES 1600000
#define F 128
#define NGRAPH 64
#define FULLMASK 0xffffffffu

// ---------------- scratch (device globals; no allocations) ----------------
__device__ float g_dinv[N_NODES];
__device__ int   g_deg[N_NODES];
__device__ int   g_ptr[N_NODES + 1];
__device__ int   g_cursor[N_NODES];
__device__ int   g_bsum[128];
__device__ int2  g_csr[N_EDGES];          // {src, norm as float bits}
__device__ float g_xw [(size_t)N_NODES * F];
__device__ float g_h  [(size_t)N_NODES * F];
__device__ float g_pool[NGRAPH * F];

// ---------------- helpers ----------------
__device__ __forceinline__ void fma2(unsigned long long& c, unsigned long long a,
                                     unsigned long long b) {
    asm("fma.rn.f32x2 %0, %1, %2, %0;" : "+l"(c) : "l"(a), "l"(b));
}
__device__ __forceinline__ unsigned long long pack2(float a) {
    unsigned long long r;
    asm("mov.b64 %0, {%1, %1};" : "=l"(r) : "f"(a));
    return r;
}
__device__ __forceinline__ float2 unpack2(unsigned long long v) {
    float2 r;
    asm("mov.b64 {%0, %1}, %2;" : "=f"(r.x), "=f"(r.y) : "l"(v));
    return r;
}

// ---------------- small kernels ----------------
__global__ void k_zero_i(int* p, int n) {
    int i = blockIdx.x * blockDim.x + threadIdx.x;
    int stride = gridDim.x * blockDim.x;
    for (; i < n; i += stride) p[i] = 0;
}
__global__ void k_zero_f4(float4* p, int n4) {
    int i = blockIdx.x * blockDim.x + threadIdx.x;
    if (i < n4) p[i] = make_float4(0.f, 0.f, 0.f, 0.f);
}
__global__ void k_degree(const int* __restrict__ col) {
    int i = blockIdx.x * blockDim.x + threadIdx.x;
    int stride = gridDim.x * blockDim.x;
    for (; i < N_EDGES; i += stride) atomicAdd(&g_deg[col[i]], 1);
}
__global__ void k_dinv() {
    int i = blockIdx.x * blockDim.x + threadIdx.x;
    if (i < N_NODES) g_dinv[i] = rsqrtf((float)g_deg[i] + 2.0f);
}

// ---------------- prefix scan over deg -> ptr ----------------
__global__ void k_scan_local() {
    __shared__ int wsum[32];
    int tid = threadIdx.x, lane = tid & 31, wid = tid >> 5;
    int i = blockIdx.x * 1024 + tid;
    int v = (i < N_NODES) ? g_deg[i] : 0;
    int x = v;
    #pragma unroll
    for (int d = 1; d < 32; d <<= 1) {
        int y = __shfl_up_sync(FULLMASK, x, d);
        if (lane >= d) x += y;
    }
    if (lane == 31) wsum[wid] = x;
    __syncthreads();
    if (wid == 0) {
        int w = wsum[lane];
        int xx = w;
        #pragma unroll
        for (int d = 1; d < 32; d <<= 1) {
            int y = __shfl_up_sync(FULLMASK, xx, d);
            if (lane >= d) xx += y;
        }
        wsum[lane] = xx - w;                    // exclusive warp offsets
        if (lane == 31) g_bsum[blockIdx.x] = xx; // block total
    }
    __syncthreads();
    if (i < N_NODES) g_ptr[i] = x - v + wsum[wid];
}
__global__ void k_scan_bsum(int nb) {
    __shared__ int s[128];
    int t = threadIdx.x;
    s[t] = (t < nb) ? g_bsum[t] : 0;
    __syncthreads();
    if (t == 0) {
        int acc = 0;
        for (int i = 0; i < nb; i++) { int v = s[i]; s[i] = acc; acc += v; }
    }
    __syncthreads();
    if (t < nb) g_bsum[t] = s[t];
}
__global__ void k_scan_add() {
    int i = blockIdx.x * 1024 + threadIdx.x;
    if (i < N_NODES) {
        int p = g_ptr[i] + g_bsum[blockIdx.x];
        g_ptr[i] = p;
        g_cursor[i] = p;
    }
    if (i == 0) g_ptr[N_NODES] = N_EDGES;
}

// ---------------- CSR fill: bucket edges by col ----------------
__global__ void k_fill(const int* __restrict__ row, const int* __restrict__ col) {
    int i = blockIdx.x * blockDim.x + threadIdx.x;
    int stride = gridDim.x * blockDim.x;
    for (; i < N_EDGES; i += stride) {
        int r = row[i];
        int c = col[i];
        float nrm = g_dinv[r] * g_dinv[c];
        int pos = atomicAdd(&g_cursor[c], 1);
        g_csr[pos] = make_int2(r, __float_as_int(nrm));
    }
}

// ---------------- GEMM: C[M,128] = A[M,128] @ W[128,128] (fp32, f32x2 packed) ----
#define GEMM_SMEM ((64 * 129 + 128 * 128) * 4)
__global__ void k_gemm(const float* __restrict__ A, const float* __restrict__ W,
                       float* __restrict__ C, int M) {
    extern __shared__ float sm[];
    float* As = sm;               // 64 x 129 (padded)
    float* Ws = sm + 64 * 129;    // 128 x 128
    const int t  = threadIdx.x;   // 256 threads
    const int m0 = blockIdx.x * 64;

    #pragma unroll 4
    for (int i = t; i < 128 * 32; i += 256)
        ((float4*)Ws)[i] = ((const float4*)W)[i];

    for (int i = t; i < 64 * 32; i += 256) {
        int r = i >> 5, c = i & 31;
        float4 v = make_float4(0.f, 0.f, 0.f, 0.f);
        if (m0 + r < M) v = ((const float4*)(A + (size_t)(m0 + r) * F))[c];
        float* p = As + r * 129 + c * 4;
        p[0] = v.x; p[1] = v.y; p[2] = v.z; p[3] = v.w;
    }
    __syncthreads();

    const int tx = t & 15;
    const int ty = t >> 4;

    unsigned long long acc[4][4];
    #pragma unroll
    for (int i = 0; i < 4; i++)
        #pragma unroll
        for (int j = 0; j < 4; j++) acc[i][j] = 0ULL;

    const float* a_base = As + (ty * 4) * 129;
    const float* b_base = Ws + tx * 8;

    #pragma unroll 4
    for (int k = 0; k < 128; k++) {
        unsigned long long pa0 = pack2(a_base[k]);
        unsigned long long pa1 = pack2(a_base[129 + k]);
        unsigned long long pa2 = pack2(a_base[2 * 129 + k]);
        unsigned long long pa3 = pack2(a_base[3 * 129 + k]);
        const ulonglong2* bp = (const ulonglong2*)(b_base + k * 128);
        ulonglong2 b01 = bp[0];
        ulonglong2 b23 = bp[1];
        fma2(acc[0][0], pa0, b01.x); fma2(acc[0][1], pa0, b01.y);
        fma2(acc[0][2], pa0, b23.x); fma2(acc[0][3], pa0, b23.y);
        fma2(acc[1][0], pa1, b01.x); fma2(acc[1][1], pa1, b01.y);
        fma2(acc[1][2], pa1, b23.x); fma2(acc[1][3], pa1, b23.y);
        fma2(acc[2][0], pa2, b01.x); fma2(acc[2][1], pa2, b01.y);
        fma2(acc[2][2], pa2, b23.x); fma2(acc[2][3], pa2, b23.y);
        fma2(acc[3][0], pa3, b01.x); fma2(acc[3][1], pa3, b01.y);
        fma2(acc[3][2], pa3, b23.x); fma2(acc[3][3], pa3, b23.y);
    }

    #pragma unroll
    for (int i = 0; i < 4; i++) {
        int r = m0 + ty * 4 + i;
        if (r < M) {
            float2 v0 = unpack2(acc[i][0]);
            float2 v1 = unpack2(acc[i][1]);
            float2 v2 = unpack2(acc[i][2]);
            float2 v3 = unpack2(acc[i][3]);
            float4* dst = (float4*)(C + (size_t)r * F + tx * 8);
            dst[0] = make_float4(v0.x, v0.y, v1.x, v1.y);
            dst[1] = make_float4(v2.x, v2.y, v3.x, v3.y);
        }
    }
}

// ---------------- aggregation: warp per node, gather CSR ----------------
// acc = 2*dinv[n]^2 * xw[n] + sum_{e in} nrm_e * xw[src_e]; +bias; relu.
// LAYER2: also dropout (*mask*2) and fused segment-max pool via atomicMax.
template<bool LAYER2>
__global__ void k_agg(const float4* __restrict__ xw4, const float* __restrict__ bias,
                      float4* __restrict__ out, const int4* __restrict__ mask4,
                      const int* __restrict__ batch) {
    int gw = (blockIdx.x * blockDim.x + threadIdx.x) >> 5;
    if (gw >= N_NODES) return;
    const int lane = threadIdx.x & 31;
    const int n = gw;
    const int beg = __ldg(&g_ptr[n]);
    const int end = __ldg(&g_ptr[n + 1]);
    const float dc = __ldg(&g_dinv[n]);

    float4 self = xw4[n * 32 + lane];
    float s2 = 2.f * dc * dc;
    float4 acc = make_float4(s2 * self.x, s2 * self.y, s2 * self.z, s2 * self.w);

    for (int e0 = beg; e0 < end; e0 += 32) {
        int cnt = min(32, end - e0);
        int2 pk = make_int2(0, 0);
        if (lane < cnt) pk = g_csr[e0 + lane];
        #pragma unroll 4
        for (int j = 0; j < cnt; j++) {
            int   s   = __shfl_sync(FULLMASK, pk.x, j);
            float nrm = __int_as_float(__shfl_sync(FULLMASK, pk.y, j));
            float4 v = xw4[s * 32 + lane];
            acc.x = fmaf(nrm, v.x, acc.x);
            acc.y = fmaf(nrm, v.y, acc.y);
            acc.z = fmaf(nrm, v.z, acc.z);
            acc.w = fmaf(nrm, v.w, acc.w);
        }
    }

    float4 bv = ((const float4*)bias)[lane];
    acc.x = fmaxf(acc.x + bv.x, 0.f);
    acc.y = fmaxf(acc.y + bv.y, 0.f);
    acc.z = fmaxf(acc.z + bv.z, 0.f);
    acc.w = fmaxf(acc.w + bv.w, 0.f);

    if (!LAYER2) {
        out[n * 32 + lane] = acc;
    } else {
        int4 m = mask4[n * 32 + lane];
        acc.x *= (float)(m.x << 1);
        acc.y *= (float)(m.y << 1);
        acc.z *= (float)(m.z << 1);
        acc.w *= (float)(m.w << 1);
        int* pp = (int*)(g_pool + batch[n] * F + lane * 4);
        atomicMax(pp + 0, __float_as_int(acc.x));
        atomicMax(pp + 1, __float_as_int(acc.y));
        atomicMax(pp + 2, __float_as_int(acc.z));
        atomicMax(pp + 3, __float_as_int(acc.w));
    }
}

// ---------------- head: relu(pool @ Wm + bm) @ Wf + bf -> out[64,32] ----------
__global__ void k_head(const float* __restrict__ Wm, const float* __restrict__ bm,
                       const float* __restrict__ Wf, const float* __restrict__ bf,
                       float* __restrict__ out) {
    __shared__ float sh[NGRAPH * F];
    int t = threadIdx.x;               // 256
    for (int i = t; i < NGRAPH * F; i += 256) {
        int g = i >> 7, f = i & 127;
        float acc = bm[f];
        const float* pg = g_pool + g * F;
        #pragma unroll 8
        for (int k = 0; k < 128; k++) acc = fmaf(pg[k], Wm[k * F + f], acc);
        sh[i] = fmaxf(acc, 0.f);
    }
    __syncthreads();
    for (int i = t; i < NGRAPH * 32; i += 256) {
        int g = i >> 5, o = i & 31;
        float acc = bf[o];
        const float* hg = sh + g * F;
        #pragma unroll 8
        for (int k = 0; k < 128; k++) acc = fmaf(hg[k], Wf[k * 32 + o], acc);
        out[i] = acc;
    }
}

// ---------------- launch ----------------
extern "C" void kernel_launch(void* const* d_in, const int* in_sizes, int n_in,
                              void* d_out, int out_size) {
    const float* x     = (const float*)d_in[0];
    const int*   ei    = (const int*)d_in[1];
    const int*   batch = (const int*)d_in[2];
    const int*   mask  = (const int*)d_in[3];
    const float* W1    = (const float*)d_in[4];
    const float* b1    = (const float*)d_in[5];
    const float* W2    = (const float*)d_in[6];
    const float* b2    = (const float*)d_in[7];
    const float* Wm    = (const float*)d_in[8];
    const float* bm    = (const float*)d_in[9];
    const float* Wf    = (const float*)d_in[10];
    const float* bf    = (const float*)d_in[11];
    float* out = (float*)d_out;
    (void)in_sizes; (void)n_in; (void)out_size;

    float *xw, *h, *pool;
    int* deg;
    cudaGetSymbolAddress((void**)&xw,   g_xw);
    cudaGetSymbolAddress((void**)&h,    g_h);
    cudaGetSymbolAddress((void**)&pool, g_pool);
    cudaGetSymbolAddress((void**)&deg,  g_deg);

    cudaFuncSetAttribute(k_gemm, cudaFuncAttributeMaxDynamicSharedMemorySize, GEMM_SMEM);

    const int* row = ei;
    const int* col = ei + N_EDGES;

    const int NB = (N_NODES + 1023) / 1024;           // 98 scan blocks
    const int gemm_blocks = (N_NODES + 63) / 64;      // 1563
    const int agg_blocks  = (N_NODES * 32 + 255) / 256; // warp per node, 256 thr

    // ---- setup: degrees, dinv, CSR ----
    k_zero_i<<<(N_NODES + 1023) / 1024, 1024>>>(deg, N_NODES);
    k_zero_f4<<<8, 256>>>((float4*)pool, NGRAPH * F / 4);
    k_degree<<<1184, 256>>>(col);
    k_dinv<<<(N_NODES + 255) / 256, 256>>>();
    k_scan_local<<<NB, 1024>>>();
    k_scan_bsum<<<1, 128>>>(NB);
    k_scan_add<<<NB, 1024>>>();
    k_fill<<<1184, 256>>>(row, col);

    // ---- layer 1: xw = x@W1; h = relu(agg(xw) + b1) ----
    k_gemm<<<gemm_blocks, 256, GEMM_SMEM>>>(x, W1, xw, N_NODES);
    k_agg<false><<<agg_blocks, 256>>>((const float4*)xw, b1, (float4*)h,
                                      nullptr, nullptr);

    // ---- layer 2: xw = h@W2; fused agg + b2 + relu + dropout + max-pool ----
    k_gemm<<<gemm_blocks, 256, GEMM_SMEM>>>(h, W2, xw, N_NODES);
    k_agg<true><<<agg_blocks, 256>>>((const float4*)xw, b2, nullptr,
                                     (const int4*)mask, batch);

    // ---- MLP head ----
    k_head<<<1, 256>>>(Wm, bm, Wf, bf, out);
}

// round 4
// speedup vs baseline: 1.3486x; 1.3486x over previous
#include <cuda_runtime.h>

#define N_NODES 100000
#define N_EDGES 1600000
#define F 128
#define NGRAPH 64
#define FULLMASK 0xffffffffu

// ---------------- scratch (device globals; no allocations) ----------------
__device__ float g_dinv[N_NODES];
__device__ int   g_deg[N_NODES];
__device__ float g_xw [(size_t)N_NODES * F];
__device__ float g_agg[(size_t)N_NODES * F];
__device__ float g_pool[NGRAPH * F];

// ---------------- helpers ----------------
__device__ __forceinline__ void fma2(unsigned long long& c, unsigned long long a,
                                     unsigned long long b) {
    asm("fma.rn.f32x2 %0, %1, %2, %0;" : "+l"(c) : "l"(a), "l"(b));
}
__device__ __forceinline__ unsigned long long pack2(float a) {
    unsigned long long r;
    asm("mov.b64 %0, {%1, %1};" : "=l"(r) : "f"(a));
    return r;
}
__device__ __forceinline__ float2 unpack2(unsigned long long v) {
    float2 r;
    asm("mov.b64 {%0, %1}, %2;" : "=f"(r.x), "=f"(r.y) : "l"(v));
    return r;
}

// ---------------- small kernels ----------------
__global__ void k_zero_i(int* p, int n) {
    int i = blockIdx.x * blockDim.x + threadIdx.x;
    if (i < n) p[i] = 0;
}
__global__ void k_zero_f4(float4* p, int n4) {
    int i = blockIdx.x * blockDim.x + threadIdx.x;
    if (i < n4) p[i] = make_float4(0.f, 0.f, 0.f, 0.f);
}
__global__ void k_degree(const int* __restrict__ col) {
    int i = blockIdx.x * blockDim.x + threadIdx.x;
    int stride = gridDim.x * blockDim.x;
    for (; i < N_EDGES; i += stride) atomicAdd(&g_deg[col[i]], 1);
}
__global__ void k_dinv() {
    int i = blockIdx.x * blockDim.x + threadIdx.x;
    if (i < N_NODES) g_dinv[i] = rsqrtf((float)g_deg[i] + 2.0f);
}

// ---------------- GEMM: C[M,128] = A[M,128] @ W[128,128] ----------------
// Optionally applies relu to A elements at load time (fuses prior layer's relu).
#define GEMM_SMEM ((64 * 129 + 128 * 128) * 4)
template<bool RELU_A>
__global__ void k_gemm(const float* __restrict__ A, const float* __restrict__ W,
                       float* __restrict__ C, int M) {
    extern __shared__ float sm[];
    float* As = sm;               // 64 x 129 (padded)
    float* Ws = sm + 64 * 129;    // 128 x 128
    const int t  = threadIdx.x;   // 256 threads
    const int m0 = blockIdx.x * 64;

    #pragma unroll 4
    for (int i = t; i < 128 * 32; i += 256)
        ((float4*)Ws)[i] = ((const float4*)W)[i];

    for (int i = t; i < 64 * 32; i += 256) {
        int r = i >> 5, c = i & 31;
        float4 v = make_float4(0.f, 0.f, 0.f, 0.f);
        if (m0 + r < M) v = ((const float4*)(A + (size_t)(m0 + r) * F))[c];
        if (RELU_A) {
            v.x = fmaxf(v.x, 0.f); v.y = fmaxf(v.y, 0.f);
            v.z = fmaxf(v.z, 0.f); v.w = fmaxf(v.w, 0.f);
        }
        float* p = As + r * 129 + c * 4;
        p[0] = v.x; p[1] = v.y; p[2] = v.z; p[3] = v.w;
    }
    __syncthreads();

    const int tx = t & 15;
    const int ty = t >> 4;

    unsigned long long acc[4][4];
    #pragma unroll
    for (int i = 0; i < 4; i++)
        #pragma unroll
        for (int j = 0; j < 4; j++) acc[i][j] = 0ULL;

    const float* a_base = As + (ty * 4) * 129;
    const float* b_base = Ws + tx * 8;

    #pragma unroll 4
    for (int k = 0; k < 128; k++) {
        unsigned long long pa0 = pack2(a_base[k]);
        unsigned long long pa1 = pack2(a_base[129 + k]);
        unsigned long long pa2 = pack2(a_base[2 * 129 + k]);
        unsigned long long pa3 = pack2(a_base[3 * 129 + k]);
        const ulonglong2* bp = (const ulonglong2*)(b_base + k * 128);
        ulonglong2 b01 = bp[0];
        ulonglong2 b23 = bp[1];
        fma2(acc[0][0], pa0, b01.x); fma2(acc[0][1], pa0, b01.y);
        fma2(acc[0][2], pa0, b23.x); fma2(acc[0][3], pa0, b23.y);
        fma2(acc[1][0], pa1, b01.x); fma2(acc[1][1], pa1, b01.y);
        fma2(acc[1][2], pa1, b23.x); fma2(acc[1][3], pa1, b23.y);
        fma2(acc[2][0], pa2, b01.x); fma2(acc[2][1], pa2, b01.y);
        fma2(acc[2][2], pa2, b23.x); fma2(acc[2][3], pa2, b23.y);
        fma2(acc[3][0], pa3, b01.x); fma2(acc[3][1], pa3, b01.y);
        fma2(acc[3][2], pa3, b23.x); fma2(acc[3][3], pa3, b23.y);
    }

    #pragma unroll
    for (int i = 0; i < 4; i++) {
        int r = m0 + ty * 4 + i;
        if (r < M) {
            float2 v0 = unpack2(acc[i][0]);
            float2 v1 = unpack2(acc[i][1]);
            float2 v2 = unpack2(acc[i][2]);
            float2 v3 = unpack2(acc[i][3]);
            float4* dst = (float4*)(C + (size_t)r * F + tx * 8);
            dst[0] = make_float4(v0.x, v0.y, v1.x, v1.y);
            dst[1] = make_float4(v2.x, v2.y, v3.x, v3.y);
        }
    }
}

// ---------------- init: agg = 2*dinv^2 * xw + bias (replaces zero + post) ----
__global__ void k_init(const float4* __restrict__ xw4, const float* __restrict__ bias,
                       float4* __restrict__ agg4) {
    int i = blockIdx.x * blockDim.x + threadIdx.x;
    int stride = gridDim.x * blockDim.x;
    const int n4 = N_NODES * 32;
    for (; i < n4; i += stride) {
        int node = i >> 5;
        int c4   = i & 31;
        float d = g_dinv[node];
        float s = 2.f * d * d;
        float4 xv = xw4[i];
        float4 bv = ((const float4*)bias)[c4];
        float4 o;
        o.x = fmaf(s, xv.x, bv.x);
        o.y = fmaf(s, xv.y, bv.y);
        o.z = fmaf(s, xv.z, bv.z);
        o.w = fmaf(s, xv.w, bv.w);
        agg4[i] = o;
    }
}

// ---------------- edge scatter: agg[col] += dinv[row]*dinv[col] * xw[row] ----
// warp per edge pair (2-way unroll for MLP); lane owns one float4;
// vectorized fire-and-forget red.global.add.
__global__ void k_edge(const int* __restrict__ row, const int* __restrict__ col,
                       const float* __restrict__ src, float* __restrict__ dst) {
    int warp  = (blockIdx.x * blockDim.x + threadIdx.x) >> 5;
    int lane  = threadIdx.x & 31;
    int nwarp = (gridDim.x * blockDim.x) >> 5;
    // N_EDGES even; warp*2 start + even stride keeps e+1 in range
    for (int e = warp * 2; e < N_EDGES; e += nwarp * 2) {
        int r0 = row[e],     c0 = col[e];
        int r1 = row[e + 1], c1 = col[e + 1];
        float n0 = g_dinv[r0] * g_dinv[c0];
        float n1 = g_dinv[r1] * g_dinv[c1];
        float4 v0 = ((const float4*)(src + ((size_t)r0 << 7)))[lane];
        float4 v1 = ((const float4*)(src + ((size_t)r1 << 7)))[lane];
        v0.x *= n0; v0.y *= n0; v0.z *= n0; v0.w *= n0;
        v1.x *= n1; v1.y *= n1; v1.z *= n1; v1.w *= n1;
        float* a0 = dst + ((size_t)c0 << 7) + lane * 4;
        float* a1 = dst + ((size_t)c1 << 7) + lane * 4;
        asm volatile("red.global.add.v4.f32 [%0], {%1, %2, %3, %4};"
                     :: "l"(a0), "f"(v0.x), "f"(v0.y), "f"(v0.z), "f"(v0.w)
                     : "memory");
        asm volatile("red.global.add.v4.f32 [%0], {%1, %2, %3, %4};"
                     :: "l"(a1), "f"(v1.x), "f"(v1.y), "f"(v1.z), "f"(v1.w)
                     : "memory");
    }
}

// ---------------- relu + dropout + segment-max pool (reads agg directly) ----
// block = 128 threads (one per feature), 64 consecutive nodes; batch sorted.
// values >= 0 -> int-bit atomicMax with 0-init is exact.
__global__ void k_pool(const float* __restrict__ agg, const int* __restrict__ mask,
                       const int* __restrict__ batch) {
    int t  = threadIdx.x;           // feature
    int n0 = blockIdx.x * 64;
    int cur = -1;
    float mx = 0.f;
    for (int i = 0; i < 64; i++) {
        int n = n0 + i;
        if (n >= N_NODES) break;
        int bid = batch[n];
        if (bid != cur) {
            if (cur >= 0) atomicMax((int*)&g_pool[cur * F + t], __float_as_int(mx));
            cur = bid;
            mx = 0.f;
        }
        size_t idx = (size_t)n * F + t;
        float v = fmaxf(agg[idx], 0.f);
        v *= (float)(mask[idx] << 1);   // dropout: *mask*2
        mx = fmaxf(mx, v);
    }
    if (cur >= 0) atomicMax((int*)&g_pool[cur * F + t], __float_as_int(mx));
}

// ---------------- head: relu(pool @ Wm + bm) @ Wf + bf -> out[64,32] ----------
__global__ void k_head(const float* __restrict__ Wm, const float* __restrict__ bm,
                       const float* __restrict__ Wf, const float* __restrict__ bf,
                       float* __restrict__ out) {
    __shared__ float sh[NGRAPH * F];
    int t = threadIdx.x;               // 256
    for (int i = t; i < NGRAPH * F; i += 256) {
        int g = i >> 7, f = i & 127;
        float acc = bm[f];
        const float* pg = g_pool + g * F;
        #pragma unroll 8
        for (int k = 0; k < 128; k++) acc = fmaf(pg[k], Wm[k * F + f], acc);
        sh[i] = fmaxf(acc, 0.f);
    }
    __syncthreads();
    for (int i = t; i < NGRAPH * 32; i += 256) {
        int g = i >> 5, o = i & 31;
        float acc = bf[o];
        const float* hg = sh + g * F;
        #pragma unroll 8
        for (int k = 0; k < 128; k++) acc = fmaf(hg[k], Wf[k * 32 + o], acc);
        out[i] = acc;
    }
}

// ---------------- launch ----------------
extern "C" void kernel_launch(void* const* d_in, const int* in_sizes, int n_in,
                              void* d_out, int out_size) {
    const float* x     = (const float*)d_in[0];
    const int*   ei    = (const int*)d_in[1];
    const int*   batch = (const int*)d_in[2];
    const int*   mask  = (const int*)d_in[3];
    const float* W1    = (const float*)d_in[4];
    const float* b1    = (const float*)d_in[5];
    const float* W2    = (const float*)d_in[6];
    const float* b2    = (const float*)d_in[7];
    const float* Wm    = (const float*)d_in[8];
    const float* bm    = (const float*)d_in[9];
    const float* Wf    = (const float*)d_in[10];
    const float* bf    = (const float*)d_in[11];
    float* out = (float*)d_out;
    (void)in_sizes; (void)n_in; (void)out_size;

    float *xw, *agg, *pool;
    int* deg;
    cudaGetSymbolAddress((void**)&xw,   g_xw);
    cudaGetSymbolAddress((void**)&agg,  g_agg);
    cudaGetSymbolAddress((void**)&pool, g_pool);
    cudaGetSymbolAddress((void**)&deg,  g_deg);

    cudaFuncSetAttribute(k_gemm<false>, cudaFuncAttributeMaxDynamicSharedMemorySize, GEMM_SMEM);
    cudaFuncSetAttribute(k_gemm<true>,  cudaFuncAttributeMaxDynamicSharedMemorySize, GEMM_SMEM);

    const int* row = ei;
    const int* col = ei + N_EDGES;

    const int gemm_blocks = (N_NODES + 63) / 64;        // 1563
    const int pool_blocks = (N_NODES + 63) / 64;        // 1563
    const int init_blocks = 2048;                       // grid-stride over 3.2M f4
    const int edge_blocks = 2368;                       // ~19k warps, 2 edges/iter

    // ---- setup ----
    k_zero_i<<<(N_NODES + 255) / 256, 256>>>(deg, N_NODES);
    k_zero_f4<<<8, 256>>>((float4*)pool, NGRAPH * F / 4);
    k_degree<<<1184, 256>>>(col);
    k_dinv<<<(N_NODES + 255) / 256, 256>>>();

    // ---- layer 1 ----
    k_gemm<false><<<gemm_blocks, 256, GEMM_SMEM>>>(x, W1, xw, N_NODES);
    k_init<<<init_blocks, 256>>>((const float4*)xw, b1, (float4*)agg);
    k_edge<<<edge_blocks, 256>>>(row, col, xw, agg);

    // ---- layer 2 (relu of layer-1 result fused into GEMM A load) ----
    k_gemm<true><<<gemm_blocks, 256, GEMM_SMEM>>>(agg, W2, xw, N_NODES);
    k_init<<<init_blocks, 256>>>((const float4*)xw, b2, (float4*)agg);
    k_edge<<<edge_blocks, 256>>>(row, col, xw, agg);

    // ---- relu + dropout + max-pool ----
    k_pool<<<pool_blocks, 128>>>(agg, mask, batch);

    // ---- MLP head ----
    k_head<<<1, 256>>>(Wm, bm, Wf, bf, out);
}

// round 5
// speedup vs baseline: 1.3652x; 1.0123x over previous
#include <cuda_runtime.h>

#define N_NODES 100000
#define N_EDGES 1600000
#define F 128
#define NGRAPH 64
#define FULLMASK 0xffffffffu

// ---------------- scratch (device globals; no allocations) ----------------
__device__ float g_dinv[N_NODES];
__device__ int   g_deg[N_NODES];
__device__ float g_xw [(size_t)N_NODES * F];
__device__ float g_agg[(size_t)N_NODES * F];
__device__ float g_pool[NGRAPH * F];

// ---------------- helpers ----------------
__device__ __forceinline__ void fma2(unsigned long long& c, unsigned long long a,
                                     unsigned long long b) {
    asm("fma.rn.f32x2 %0, %1, %2, %0;" : "+l"(c) : "l"(a), "l"(b));
}
__device__ __forceinline__ unsigned long long pack2(float a) {
    unsigned long long r;
    asm("mov.b64 %0, {%1, %1};" : "=l"(r) : "f"(a));
    return r;
}
__device__ __forceinline__ float2 unpack2(unsigned long long v) {
    float2 r;
    asm("mov.b64 {%0, %1}, %2;" : "=f"(r.x), "=f"(r.y) : "l"(v));
    return r;
}

// ---------------- small kernels ----------------
__global__ void k_zero_i(int* p, int n) {
    int i = blockIdx.x * blockDim.x + threadIdx.x;
    if (i < n) p[i] = 0;
}
__global__ void k_zero_f4(float4* p, int n4) {
    int i = blockIdx.x * blockDim.x + threadIdx.x;
    if (i < n4) p[i] = make_float4(0.f, 0.f, 0.f, 0.f);
}
__global__ void k_degree(const int* __restrict__ col) {
    int i = blockIdx.x * blockDim.x + threadIdx.x;
    int stride = gridDim.x * blockDim.x;
    for (; i < N_EDGES; i += stride) atomicAdd(&g_deg[col[i]], 1);
}
__global__ void k_dinv() {
    int i = blockIdx.x * blockDim.x + threadIdx.x;
    if (i < N_NODES) g_dinv[i] = rsqrtf((float)g_deg[i] + 2.0f);
}

// ---- GEMM + fused init epilogue:
//   xw  = (RELU_A ? relu(A) : A) @ W
//   agg = 2*dinv^2 * xw + bias          (self-loop term + bias, pre-seeds scatter)
#define GEMM_SMEM ((64 * 129 + 128 * 128) * 4)
template<bool RELU_A>
__global__ void k_gemm_init(const float* __restrict__ A, const float* __restrict__ W,
                            const float* __restrict__ bias,
                            float* __restrict__ xw, float* __restrict__ agg, int M) {
    extern __shared__ float sm[];
    float* As = sm;               // 64 x 129 (padded)
    float* Ws = sm + 64 * 129;    // 128 x 128
    const int t  = threadIdx.x;   // 256 threads
    const int m0 = blockIdx.x * 64;

    #pragma unroll 4
    for (int i = t; i < 128 * 32; i += 256)
        ((float4*)Ws)[i] = ((const float4*)W)[i];

    for (int i = t; i < 64 * 32; i += 256) {
        int r = i >> 5, c = i & 31;
        float4 v = make_float4(0.f, 0.f, 0.f, 0.f);
        if (m0 + r < M) v = ((const float4*)(A + (size_t)(m0 + r) * F))[c];
        if (RELU_A) {
            v.x = fmaxf(v.x, 0.f); v.y = fmaxf(v.y, 0.f);
            v.z = fmaxf(v.z, 0.f); v.w = fmaxf(v.w, 0.f);
        }
        float* p = As + r * 129 + c * 4;
        p[0] = v.x; p[1] = v.y; p[2] = v.z; p[3] = v.w;
    }
    __syncthreads();

    const int tx = t & 15;   // cols tx*8 .. tx*8+7
    const int ty = t >> 4;   // rows ty*4 .. ty*4+3

    unsigned long long acc[4][4];
    #pragma unroll
    for (int i = 0; i < 4; i++)
        #pragma unroll
        for (int j = 0; j < 4; j++) acc[i][j] = 0ULL;

    const float* a_base = As + (ty * 4) * 129;
    const float* b_base = Ws + tx * 8;

    #pragma unroll 4
    for (int k = 0; k < 128; k++) {
        unsigned long long pa0 = pack2(a_base[k]);
        unsigned long long pa1 = pack2(a_base[129 + k]);
        unsigned long long pa2 = pack2(a_base[2 * 129 + k]);
        unsigned long long pa3 = pack2(a_base[3 * 129 + k]);
        const ulonglong2* bp = (const ulonglong2*)(b_base + k * 128);
        ulonglong2 b01 = bp[0];
        ulonglong2 b23 = bp[1];
        fma2(acc[0][0], pa0, b01.x); fma2(acc[0][1], pa0, b01.y);
        fma2(acc[0][2], pa0, b23.x); fma2(acc[0][3], pa0, b23.y);
        fma2(acc[1][0], pa1, b01.x); fma2(acc[1][1], pa1, b01.y);
        fma2(acc[1][2], pa1, b23.x); fma2(acc[1][3], pa1, b23.y);
        fma2(acc[2][0], pa2, b01.x); fma2(acc[2][1], pa2, b01.y);
        fma2(acc[2][2], pa2, b23.x); fma2(acc[2][3], pa2, b23.y);
        fma2(acc[3][0], pa3, b01.x); fma2(acc[3][1], pa3, b01.y);
        fma2(acc[3][2], pa3, b23.x); fma2(acc[3][3], pa3, b23.y);
    }

    // bias for this thread's 8 columns
    float4 bv0 = ((const float4*)bias)[tx * 2];
    float4 bv1 = ((const float4*)bias)[tx * 2 + 1];

    #pragma unroll
    for (int i = 0; i < 4; i++) {
        int r = m0 + ty * 4 + i;
        if (r < M) {
            float2 v0 = unpack2(acc[i][0]);
            float2 v1 = unpack2(acc[i][1]);
            float2 v2 = unpack2(acc[i][2]);
            float2 v3 = unpack2(acc[i][3]);
            float4 o0 = make_float4(v0.x, v0.y, v1.x, v1.y);
            float4 o1 = make_float4(v2.x, v2.y, v3.x, v3.y);
            float4* xdst = (float4*)(xw + (size_t)r * F + tx * 8);
            xdst[0] = o0;
            xdst[1] = o1;
            float d = g_dinv[r];
            float s = 2.f * d * d;
            float4 a0, a1;
            a0.x = fmaf(s, o0.x, bv0.x); a0.y = fmaf(s, o0.y, bv0.y);
            a0.z = fmaf(s, o0.z, bv0.z); a0.w = fmaf(s, o0.w, bv0.w);
            a1.x = fmaf(s, o1.x, bv1.x); a1.y = fmaf(s, o1.y, bv1.y);
            a1.z = fmaf(s, o1.z, bv1.z); a1.w = fmaf(s, o1.w, bv1.w);
            float4* adst = (float4*)(agg + (size_t)r * F + tx * 8);
            adst[0] = a0;
            adst[1] = a1;
        }
    }
}

// ---------------- edge scatter: agg[col] += dinv[row]*dinv[col] * xw[row] ----
// one warp handles 4 edges (one-shot, exact grid); lane owns one float4;
// 4 gathers issued back-to-back for MLP, then 4 fire-and-forget red.v4.
__global__ void k_edge(const int* __restrict__ row, const int* __restrict__ col,
                       const float* __restrict__ src, float* __restrict__ dst) {
    int warp = (blockIdx.x * blockDim.x + threadIdx.x) >> 5;
    int lane = threadIdx.x & 31;
    int e = warp * 4;
    if (e >= N_EDGES) return;   // N_EDGES % 4 == 0 -> full quad or nothing

    int r0 = __ldg(row + e),     c0 = __ldg(col + e);
    int r1 = __ldg(row + e + 1), c1 = __ldg(col + e + 1);
    int r2 = __ldg(row + e + 2), c2 = __ldg(col + e + 2);
    int r3 = __ldg(row + e + 3), c3 = __ldg(col + e + 3);

    const float4* s0 = (const float4*)(src + ((size_t)r0 << 7));
    const float4* s1 = (const float4*)(src + ((size_t)r1 << 7));
    const float4* s2 = (const float4*)(src + ((size_t)r2 << 7));
    const float4* s3 = (const float4*)(src + ((size_t)r3 << 7));
    float4 v0 = __ldg(s0 + lane);
    float4 v1 = __ldg(s1 + lane);
    float4 v2 = __ldg(s2 + lane);
    float4 v3 = __ldg(s3 + lane);

    float n0 = g_dinv[r0] * g_dinv[c0];
    float n1 = g_dinv[r1] * g_dinv[c1];
    float n2 = g_dinv[r2] * g_dinv[c2];
    float n3 = g_dinv[r3] * g_dinv[c3];

    v0.x *= n0; v0.y *= n0; v0.z *= n0; v0.w *= n0;
    v1.x *= n1; v1.y *= n1; v1.z *= n1; v1.w *= n1;
    v2.x *= n2; v2.y *= n2; v2.z *= n2; v2.w *= n2;
    v3.x *= n3; v3.y *= n3; v3.z *= n3; v3.w *= n3;

    float* a0 = dst + ((size_t)c0 << 7) + lane * 4;
    float* a1 = dst + ((size_t)c1 << 7) + lane * 4;
    float* a2 = dst + ((size_t)c2 << 7) + lane * 4;
    float* a3 = dst + ((size_t)c3 << 7) + lane * 4;
    asm volatile("red.global.add.v4.f32 [%0], {%1, %2, %3, %4};"
                 :: "l"(a0), "f"(v0.x), "f"(v0.y), "f"(v0.z), "f"(v0.w) : "memory");
    asm volatile("red.global.add.v4.f32 [%0], {%1, %2, %3, %4};"
                 :: "l"(a1), "f"(v1.x), "f"(v1.y), "f"(v1.z), "f"(v1.w) : "memory");
    asm volatile("red.global.add.v4.f32 [%0], {%1, %2, %3, %4};"
                 :: "l"(a2), "f"(v2.x), "f"(v2.y), "f"(v2.z), "f"(v2.w) : "memory");
    asm volatile("red.global.add.v4.f32 [%0], {%1, %2, %3, %4};"
                 :: "l"(a3), "f"(v3.x), "f"(v3.y), "f"(v3.z), "f"(v3.w) : "memory");
}

// ---------------- relu + dropout + segment-max pool (reads agg directly) ----
__global__ void k_pool(const float* __restrict__ agg, const int* __restrict__ mask,
                       const int* __restrict__ batch) {
    int t  = threadIdx.x;           // feature
    int n0 = blockIdx.x * 64;
    int cur = -1;
    float mx = 0.f;
    for (int i = 0; i < 64; i++) {
        int n = n0 + i;
        if (n >= N_NODES) break;
        int bid = batch[n];
        if (bid != cur) {
            if (cur >= 0) atomicMax((int*)&g_pool[cur * F + t], __float_as_int(mx));
            cur = bid;
            mx = 0.f;
        }
        size_t idx = (size_t)n * F + t;
        float v = fmaxf(agg[idx], 0.f);
        v *= (float)(mask[idx] << 1);   // dropout: *mask*2
        mx = fmaxf(mx, v);
    }
    if (cur >= 0) atomicMax((int*)&g_pool[cur * F + t], __float_as_int(mx));
}

// ---------------- head: relu(pool @ Wm + bm) @ Wf + bf -> out[64,32] ----------
__global__ void k_head(const float* __restrict__ Wm, const float* __restrict__ bm,
                       const float* __restrict__ Wf, const float* __restrict__ bf,
                       float* __restrict__ out) {
    __shared__ float sh[NGRAPH * F];
    int t = threadIdx.x;               // 256
    for (int i = t; i < NGRAPH * F; i += 256) {
        int g = i >> 7, f = i & 127;
        float acc = bm[f];
        const float* pg = g_pool + g * F;
        #pragma unroll 8
        for (int k = 0; k < 128; k++) acc = fmaf(pg[k], Wm[k * F + f], acc);
        sh[i] = fmaxf(acc, 0.f);
    }
    __syncthreads();
    for (int i = t; i < NGRAPH * 32; i += 256) {
        int g = i >> 5, o = i & 31;
        float acc = bf[o];
        const float* hg = sh + g * F;
        #pragma unroll 8
        for (int k = 0; k < 128; k++) acc = fmaf(hg[k], Wf[k * 32 + o], acc);
        out[i] = acc;
    }
}

// ---------------- launch ----------------
extern "C" void kernel_launch(void* const* d_in, const int* in_sizes, int n_in,
                              void* d_out, int out_size) {
    const float* x     = (const float*)d_in[0];
    const int*   ei    = (const int*)d_in[1];
    const int*   batch = (const int*)d_in[2];
    const int*   mask  = (const int*)d_in[3];
    const float* W1    = (const float*)d_in[4];
    const float* b1    = (const float*)d_in[5];
    const float* W2    = (const float*)d_in[6];
    const float* b2    = (const float*)d_in[7];
    const float* Wm    = (const float*)d_in[8];
    const float* bm    = (const float*)d_in[9];
    const float* Wf    = (const float*)d_in[10];
    const float* bf    = (const float*)d_in[11];
    float* out = (float*)d_out;
    (void)in_sizes; (void)n_in; (void)out_size;

    float *xw, *agg, *pool;
    int* deg;
    cudaGetSymbolAddress((void**)&xw,   g_xw);
    cudaGetSymbolAddress((void**)&agg,  g_agg);
    cudaGetSymbolAddress((void**)&pool, g_pool);
    cudaGetSymbolAddress((void**)&deg,  g_deg);

    cudaFuncSetAttribute(k_gemm_init<false>, cudaFuncAttributeMaxDynamicSharedMemorySize, GEMM_SMEM);
    cudaFuncSetAttribute(k_gemm_init<true>,  cudaFuncAttributeMaxDynamicSharedMemorySize, GEMM_SMEM);

    const int* row = ei;
    const int* col = ei + N_EDGES;

    const int gemm_blocks = (N_NODES + 63) / 64;            // 1563
    const int pool_blocks = (N_NODES + 63) / 64;            // 1563
    const int edge_blocks = (N_EDGES / 4 + 7) / 8;          // 1 warp = 4 edges, 8 warps/blk

    // ---- setup ----
    k_zero_i<<<(N_NODES + 255) / 256, 256>>>(deg, N_NODES);
    k_zero_f4<<<8, 256>>>((float4*)pool, NGRAPH * F / 4);
    k_degree<<<1184, 256>>>(col);
    k_dinv<<<(N_NODES + 255) / 256, 256>>>();

    // ---- layer 1: xw = x@W1; agg seeded with self-term+bias; scatter edges ----
    k_gemm_init<false><<<gemm_blocks, 256, GEMM_SMEM>>>(x, W1, b1, xw, agg, N_NODES);
    k_edge<<<edge_blocks, 256>>>(row, col, xw, agg);

    // ---- layer 2 (relu of layer-1 agg fused into GEMM A load) ----
    k_gemm_init<true><<<gemm_blocks, 256, GEMM_SMEM>>>(agg, W2, b2, xw, agg, N_NODES);
    k_edge<<<edge_blocks, 256>>>(row, col, xw, agg);

    // ---- relu + dropout + max-pool ----
    k_pool<<<pool_blocks, 128>>>(agg, mask, batch);

    // ---- MLP head ----
    k_head<<<1, 256>>>(Wm, bm, Wf, bf, out);
}